// round 8
// baseline (speedup 1.0000x reference)
#include <cuda_runtime.h>
#include <cuda.h>
#include <cstdint>

#define M_TOK   16
#define K_DIM   4096
#define N_OUT   11008
#define OTILE   32
#define NCTA    (N_OUT / OTILE)     // 344
#define KT      64                  // k per stage
#define SCNT    (K_DIM / KT)        // 64 stages
#define NBUF    4
#define THREADS 256

#define WBOX0   68                  // 64 k ints + 4 pad ints
#define WSTRIDE (WBOX0 * 4)         // 272 B pitch, conflict-free phases
#define W_REGION (OTILE * WSTRIDE)  // 8704
#define XPITCH  64                  // 16 tokens * 4B, no pad
#define X_REGION (KT * XPITCH)      // 4096
#define ST_SIZE  (W_REGION + X_REGION)   // 12800
#define MBAR_OFF (NBUF * ST_SIZE)        // 51200
#define TX_BYTES ST_SIZE
#define DYN_SMEM (MBAR_OFF + NBUF * 8 + 16)

#define X_ELEMS (M_TOK * K_DIM)
#define W_ELEMS ((long long)N_OUT * K_DIM)

static __device__ __align__(16) float g_xT[K_DIM * M_TOK];  // [k][t], 64B rows
static __device__ float g_psum[M_TOK * 8];

__device__ __forceinline__ void ffma2(unsigned long long &d,
                                      unsigned long long a,
                                      unsigned long long b) {
    asm("fma.rn.f32x2 %0, %1, %2, %3;" : "=l"(d) : "l"(a), "l"(b), "l"(d));
}
__device__ __forceinline__ unsigned long long pack2(float v) {
    unsigned long long r;
    asm("mov.b64 %0, {%1, %1};" : "=l"(r) : "f"(v));
    return r;
}
__device__ __forceinline__ uint32_t smem_u32(const void* p) {
    uint32_t a;
    asm("{ .reg .u64 t; cvta.to.shared.u64 t, %1; cvt.u32.u64 %0, t; }"
        : "=r"(a) : "l"(p));
    return a;
}
__device__ __forceinline__ void mbar_init(uint32_t mbar, uint32_t cnt) {
    asm volatile("mbarrier.init.shared.b64 [%0], %1;" :: "r"(mbar), "r"(cnt) : "memory");
}
__device__ __forceinline__ void mbar_expect_tx(uint32_t mbar, uint32_t bytes) {
    asm volatile("mbarrier.arrive.expect_tx.shared.b64 _, [%0], %1;"
                 :: "r"(mbar), "r"(bytes) : "memory");
}
__device__ __forceinline__ void mbar_wait(uint32_t mbar, uint32_t parity) {
    uint32_t done;
    asm volatile(
        "{\n\t.reg .pred p;\n\t"
        "mbarrier.try_wait.parity.acquire.cta.shared::cta.b64 p, [%1], %2;\n\t"
        "selp.b32 %0, 1, 0, p;\n\t}"
        : "=r"(done) : "r"(mbar), "r"(parity) : "memory");
    if (!done) {
        asm volatile(
            "{\n\t.reg .pred P1;\n\t"
            "WL_%=:\n\t"
            "mbarrier.try_wait.parity.acquire.cta.shared::cta.b64 P1, [%0], %1, 0x989680;\n\t"
            "@P1 bra.uni WD_%=;\n\t"
            "bra.uni WL_%=;\n\t"
            "WD_%=:\n\t}"
            :: "r"(mbar), "r"(parity) : "memory");
    }
}
__device__ __forceinline__ void bulk_copy(uint32_t smem_dst, const void* gmem_src,
                                          uint32_t bytes, uint32_t mbar) {
    asm volatile(
        "cp.async.bulk.shared::cta.global.mbarrier::complete_tx::bytes "
        "[%0], [%1], %2, [%3];"
        :: "r"(smem_dst), "l"(gmem_src), "r"(bytes), "r"(mbar) : "memory");
}
__device__ __forceinline__ void tma_load_2d(uint32_t smem_dst, const void* tmap,
                                            int cx, int cy, uint32_t mbar) {
    asm volatile(
        "cp.async.bulk.tensor.2d.shared::cta.global.tile.mbarrier::complete_tx::bytes "
        "[%0], [%1, {%2, %3}], [%4];"
        :: "r"(smem_dst), "l"(tmap), "r"(cx), "r"(cy), "r"(mbar) : "memory");
}

// ---------------- prep: transpose x (64B rows) + partial row sums ----------
__global__ void prep_kernel(const float* __restrict__ x) {
    const int t = blockIdx.x & 15;          // token
    const int c = blockIdx.x >> 4;          // k-chunk 0..7 (512 k each)
    const int tid = threadIdx.x;            // 256
    __shared__ float red[256];
    float s = 0.f;
    #pragma unroll
    for (int i = 0; i < 2; i++) {
        int k = c * 512 + tid + i * 256;
        float v = x[t * K_DIM + k];
        g_xT[k * M_TOK + t] = v;
        s += v;
    }
    red[tid] = s;
    __syncthreads();
    for (int st = 128; st > 0; st >>= 1) {
        if (tid < st) red[tid] += red[tid + st];
        __syncthreads();
    }
    if (tid == 0) g_psum[t * 8 + c] = red[0];
}

// ---------------- main: 4-deep TMA pipeline, 2 rows/thread ------------------
__global__ void __launch_bounds__(THREADS, 3)
gemm_kernel(const __grid_constant__ CUtensorMap wmap,
            const float* __restrict__ scale_p,
            const int* __restrict__ zp_p,
            float* __restrict__ out)
{
    extern __shared__ __align__(16) char smem[];
    const uint32_t sbase = smem_u32(smem);
    const uint32_t mbar0 = sbase + MBAR_OFF;

    const int tid  = threadIdx.x;
    const int ks   = tid >> 5;          // warp 0..7
    const int lane = tid & 31;
    const int h    = lane >> 4;         // extra k split
    const int rg   = lane & 15;         // row group: rows rg, rg+16
    const int k0   = (ks * 2 + h) * 4;  // this thread's 4 k within the stage
    const int o_base = blockIdx.x * OTILE;

    if (tid < NBUF) mbar_init(mbar0 + tid * 8, 1);
    __syncthreads();

    // prologue: issue stages 0..3
    if (tid == 0) {
        #pragma unroll
        for (int s = 0; s < NBUF; s++) {
            const uint32_t mb = mbar0 + s * 8;
            mbar_expect_tx(mb, TX_BYTES);
            tma_load_2d(sbase + s * ST_SIZE, &wmap, s * KT, o_base, mb);
            bulk_copy(sbase + s * ST_SIZE + W_REGION,
                      g_xT + s * KT * M_TOK, X_REGION, mb);
        }
    }

    unsigned long long acc0[8], acc1[8];
    #pragma unroll
    for (int i = 0; i < 8; i++) { acc0[i] = 0ULL; acc1[i] = 0ULL; }

    #pragma unroll 1
    for (int s = 0; s < SCNT; s++) {
        const int buf = s & (NBUF - 1);
        const uint32_t phase = (s >> 2) & 1;
        mbar_wait(mbar0 + buf * 8, phase);

        const char* wbase = smem + buf * ST_SIZE;
        const char* xb    = wbase + W_REGION;
        int4 qa = *(const int4*)(wbase + rg * WSTRIDE + k0 * 4);
        int4 qb = *(const int4*)(wbase + (rg + 16) * WSTRIDE + k0 * 4);

        #pragma unroll
        for (int u = 0; u < 4; u++) {
            int iva = (u == 0) ? qa.x : (u == 1) ? qa.y : (u == 2) ? qa.z : qa.w;
            int ivb = (u == 0) ? qb.x : (u == 1) ? qb.y : (u == 2) ? qb.z : qb.w;
            float wfa = __int_as_float(iva + 0x4B400000) - 12582912.0f;
            float wfb = __int_as_float(ivb + 0x4B400000) - 12582912.0f;
            unsigned long long wa = pack2(wfa);
            unsigned long long wb2 = pack2(wfb);
            const char* xr = xb + (k0 + u) * XPITCH;
            ulonglong2 p0 = *(const ulonglong2*)(xr +  0);   // t0..3
            ulonglong2 p1 = *(const ulonglong2*)(xr + 16);   // t4..7
            ulonglong2 p2 = *(const ulonglong2*)(xr + 32);   // t8..11
            ulonglong2 p3 = *(const ulonglong2*)(xr + 48);   // t12..15
            ffma2(acc0[0], wa, p0.x);  ffma2(acc1[0], wb2, p0.x);
            ffma2(acc0[1], wa, p0.y);  ffma2(acc1[1], wb2, p0.y);
            ffma2(acc0[2], wa, p1.x);  ffma2(acc1[2], wb2, p1.x);
            ffma2(acc0[3], wa, p1.y);  ffma2(acc1[3], wb2, p1.y);
            ffma2(acc0[4], wa, p2.x);  ffma2(acc1[4], wb2, p2.x);
            ffma2(acc0[5], wa, p2.y);  ffma2(acc1[5], wb2, p2.y);
            ffma2(acc0[6], wa, p3.x);  ffma2(acc1[6], wb2, p3.x);
            ffma2(acc0[7], wa, p3.y);  ffma2(acc1[7], wb2, p3.y);
        }

        __syncthreads();                 // CTA done with buf

        if (s + NBUF < SCNT && tid == 0) {
            const uint32_t mb = mbar0 + buf * 8;
            mbar_expect_tx(mb, TX_BYTES);
            tma_load_2d(sbase + buf * ST_SIZE, &wmap, (s + NBUF) * KT, o_base, mb);
            bulk_copy(sbase + buf * ST_SIZE + W_REGION,
                      g_xT + (s + NBUF) * KT * M_TOK, X_REGION, mb);
        }
    }

    // ---- reduce 16 partials per (row, token) through smem ----
    float* part = (float*)smem;          // [(p*32 + row)*17 + t], 34.8 KB
    {
        const int p = ks * 2 + h;        // 0..15
        float* pp0 = part + ((p * 32) + rg)      * 17;
        float* pp1 = part + ((p * 32) + rg + 16) * 17;
        #pragma unroll
        for (int i = 0; i < 8; i++) {
            float lo, hi;
            asm("mov.b64 {%0, %1}, %2;" : "=f"(lo), "=f"(hi) : "l"(acc0[i]));
            pp0[2 * i] = lo;  pp0[2 * i + 1] = hi;
            asm("mov.b64 {%0, %1}, %2;" : "=f"(lo), "=f"(hi) : "l"(acc1[i]));
            pp1[2 * i] = lo;  pp1[2 * i + 1] = hi;
        }
    }
    __syncthreads();

    const float scale = *scale_p;
    const float zpf   = (float)(*zp_p);
    #pragma unroll
    for (int r = 0; r < 2; r++) {
        int idx = tid + r * THREADS;     // 0..511
        int oo  = idx & 31;
        int tt  = idx >> 5;
        float v = 0.f;
        #pragma unroll
        for (int q = 0; q < 16; q++)
            v += part[(q * 32 + oo) * 17 + tt];
        float sx = 0.f;
        #pragma unroll
        for (int c = 0; c < 8; c++) sx += g_psum[tt * 8 + c];
        out[(size_t)tt * N_OUT + o_base + oo] = scale * (v - zpf * sx);
    }
}

// ---------------- host ----------------
typedef CUresult (*EncodeTiledFn)(
    CUtensorMap*, CUtensorMapDataType, cuuint32_t, void*,
    const cuuint64_t*, const cuuint64_t*, const cuuint32_t*, const cuuint32_t*,
    CUtensorMapInterleave, CUtensorMapSwizzle, CUtensorMapL2promotion,
    CUtensorMapFloatOOBfill);

static EncodeTiledFn get_encode_fn() {
    static EncodeTiledFn fn = nullptr;
    if (fn) return fn;
    void* p = nullptr;
#if CUDART_VERSION >= 12050
    cudaDriverEntryPointQueryResult st;
    if (cudaGetDriverEntryPointByVersion("cuTensorMapEncodeTiled", &p, 12000,
                                         cudaEnableDefault, &st) != cudaSuccess)
        p = nullptr;
#endif
    if (!p) {
        cudaDriverEntryPointQueryResult st2;
        cudaGetDriverEntryPoint("cuTensorMapEncodeTiled", &p,
                                cudaEnableDefault, &st2);
    }
    fn = (EncodeTiledFn)p;
    return fn;
}

extern "C" void kernel_launch(void* const* d_in, const int* in_sizes, int n_in,
                              void* d_out, int out_size) {
    const float* x  = nullptr;
    const int*   w  = nullptr;           // int8 weights marshaled as int32
    const float* sc = nullptr;
    const int*   zp = nullptr;
    for (int i = 0; i < n_in; i++) {
        long long n = in_sizes[i];
        if (n == W_ELEMS)       w  = (const int*)d_in[i];
        else if (n == X_ELEMS)  x  = (const float*)d_in[i];
        else if (!sc)           sc = (const float*)d_in[i];
        else                    zp = (const int*)d_in[i];
    }
    (void)out_size;

    static bool attr_set = false;
    if (!attr_set) {
        cudaFuncSetAttribute(gemm_kernel,
                             cudaFuncAttributeMaxDynamicSharedMemorySize, DYN_SMEM);
        attr_set = true;
    }

    CUtensorMap wmap;
    {
        EncodeTiledFn enc = get_encode_fn();
        cuuint64_t dims[2]    = {(cuuint64_t)K_DIM, (cuuint64_t)N_OUT};
        cuuint64_t strides[1] = {(cuuint64_t)K_DIM * 4};
        cuuint32_t box[2]     = {(cuuint32_t)WBOX0, (cuuint32_t)OTILE};
        cuuint32_t estr[2]    = {1, 1};
        enc(&wmap, CU_TENSOR_MAP_DATA_TYPE_UINT32, 2, (void*)w,
            dims, strides, box, estr,
            CU_TENSOR_MAP_INTERLEAVE_NONE, CU_TENSOR_MAP_SWIZZLE_NONE,
            CU_TENSOR_MAP_L2_PROMOTION_L2_128B,
            CU_TENSOR_MAP_FLOAT_OOB_FILL_NONE);
    }

    prep_kernel<<<128, 256>>>(x);
    gemm_kernel<<<NCTA, THREADS, DYN_SMEM>>>(wmap, sc, zp, (float*)d_out);
}

// round 9
// speedup vs baseline: 1.6022x; 1.6022x over previous
#include <cuda_runtime.h>
#include <cuda.h>
#include <cstdint>

#define M_TOK   16
#define K_DIM   4096
#define N_OUT   11008
#define OTILE   32
#define NCTA    (N_OUT / OTILE)     // 344
#define KT      128                 // k per stage
#define SCNT    (K_DIM / KT)        // 32 stages
#define NBUF    2
#define THREADS 256

#define WBOX0   132                 // 128 k ints + 4 pad ints
#define WSTRIDE (WBOX0 * 4)         // 528 B pitch
#define W_REGION (OTILE * WSTRIDE)  // 16896
#define XPITCH  64                  // 16 tokens * 4B
#define X_REGION (KT * XPITCH)      // 8192
#define ST_SIZE  (W_REGION + X_REGION)   // 25088
#define MBAR_OFF (NBUF * ST_SIZE)        // 50176
#define TX_BYTES ST_SIZE
#define DYN_SMEM (MBAR_OFF + NBUF * 8 + 16)

#define X_ELEMS (M_TOK * K_DIM)
#define W_ELEMS ((long long)N_OUT * K_DIM)

static __device__ __align__(16) float g_xT[K_DIM * M_TOK];  // [k][t]
static __device__ float g_psum[M_TOK * 8];

__device__ __forceinline__ void ffma2(unsigned long long &d,
                                      unsigned long long a,
                                      unsigned long long b) {
    asm("fma.rn.f32x2 %0, %1, %2, %3;" : "=l"(d) : "l"(a), "l"(b), "l"(d));
}
__device__ __forceinline__ unsigned long long pack2(float v) {
    unsigned long long r;
    asm("mov.b64 %0, {%1, %1};" : "=l"(r) : "f"(v));
    return r;
}
__device__ __forceinline__ uint32_t smem_u32(const void* p) {
    uint32_t a;
    asm("{ .reg .u64 t; cvta.to.shared.u64 t, %1; cvt.u32.u64 %0, t; }"
        : "=r"(a) : "l"(p));
    return a;
}
__device__ __forceinline__ void mbar_init(uint32_t mbar, uint32_t cnt) {
    asm volatile("mbarrier.init.shared.b64 [%0], %1;" :: "r"(mbar), "r"(cnt) : "memory");
}
__device__ __forceinline__ void mbar_expect_tx(uint32_t mbar, uint32_t bytes) {
    asm volatile("mbarrier.arrive.expect_tx.shared.b64 _, [%0], %1;"
                 :: "r"(mbar), "r"(bytes) : "memory");
}
__device__ __forceinline__ void mbar_wait(uint32_t mbar, uint32_t parity) {
    uint32_t done;
    asm volatile(
        "{\n\t.reg .pred p;\n\t"
        "mbarrier.try_wait.parity.acquire.cta.shared::cta.b64 p, [%1], %2;\n\t"
        "selp.b32 %0, 1, 0, p;\n\t}"
        : "=r"(done) : "r"(mbar), "r"(parity) : "memory");
    if (!done) {
        asm volatile(
            "{\n\t.reg .pred P1;\n\t"
            "WL_%=:\n\t"
            "mbarrier.try_wait.parity.acquire.cta.shared::cta.b64 P1, [%0], %1, 0x989680;\n\t"
            "@P1 bra.uni WD_%=;\n\t"
            "bra.uni WL_%=;\n\t"
            "WD_%=:\n\t}"
            :: "r"(mbar), "r"(parity) : "memory");
    }
}
__device__ __forceinline__ void bulk_copy(uint32_t smem_dst, const void* gmem_src,
                                          uint32_t bytes, uint32_t mbar) {
    asm volatile(
        "cp.async.bulk.shared::cta.global.mbarrier::complete_tx::bytes "
        "[%0], [%1], %2, [%3];"
        :: "r"(smem_dst), "l"(gmem_src), "r"(bytes), "r"(mbar) : "memory");
}
__device__ __forceinline__ void tma_load_2d(uint32_t smem_dst, const void* tmap,
                                            int cx, int cy, uint32_t mbar) {
    asm volatile(
        "cp.async.bulk.tensor.2d.shared::cta.global.tile.mbarrier::complete_tx::bytes "
        "[%0], [%1, {%2, %3}], [%4];"
        :: "r"(smem_dst), "l"(tmap), "r"(cx), "r"(cy), "r"(mbar) : "memory");
}

// ---------------- prep: transpose x (64B rows) + partial row sums ----------
__global__ void prep_kernel(const float* __restrict__ x) {
    const int t = blockIdx.x & 15;          // token
    const int c = blockIdx.x >> 4;          // k-chunk 0..7 (512 k each)
    const int tid = threadIdx.x;            // 256
    __shared__ float red[256];
    float s = 0.f;
    #pragma unroll
    for (int i = 0; i < 2; i++) {
        int k = c * 512 + tid + i * 256;
        float v = x[t * K_DIM + k];
        g_xT[k * M_TOK + t] = v;
        s += v;
    }
    red[tid] = s;
    __syncthreads();
    for (int st = 128; st > 0; st >>= 1) {
        if (tid < st) red[tid] += red[tid + st];
        __syncthreads();
    }
    if (tid == 0) g_psum[t * 8 + c] = red[0];
}

// ---------------- main: 2 rows/thread, token-split lanes, I2F dequant -------
__global__ void __launch_bounds__(THREADS, 3)
gemm_kernel(const __grid_constant__ CUtensorMap wmap,
            const float* __restrict__ scale_p,
            const int* __restrict__ zp_p,
            float* __restrict__ out)
{
    extern __shared__ __align__(16) char smem[];
    const uint32_t sbase = smem_u32(smem);
    const uint32_t mbar0 = sbase + MBAR_OFF;

    const int tid  = threadIdx.x;
    const int wid  = tid >> 5;          // warp 0..7 -> k-slice of 16 k
    const int lane = tid & 31;
    const int rg   = lane & 15;         // rows rg and rg+16
    const int h    = lane >> 4;         // token half: tokens h*8 .. h*8+8
    const int o_base = blockIdx.x * OTILE;

    const float scale = *scale_p;
    const float zpf   = (float)(*zp_p);

    if (tid < NBUF) mbar_init(mbar0 + tid * 8, 1);
    __syncthreads();

    // prologue: issue stages 0..NBUF-1
    if (tid == 0) {
        #pragma unroll
        for (int s = 0; s < NBUF; s++) {
            const uint32_t mb = mbar0 + s * 8;
            mbar_expect_tx(mb, TX_BYTES);
            tma_load_2d(sbase + s * ST_SIZE, &wmap, s * KT, o_base, mb);
            bulk_copy(sbase + s * ST_SIZE + W_REGION,
                      g_xT + s * KT * M_TOK, X_REGION, mb);
        }
    }

    // acc0 = row rg, acc1 = row rg+16; 4 f32x2 each (8 tokens)
    unsigned long long acc0[4], acc1[4];
    #pragma unroll
    for (int i = 0; i < 4; i++) { acc0[i] = 0ULL; acc1[i] = 0ULL; }

    #pragma unroll 1
    for (int s = 0; s < SCNT; s++) {
        const int buf = s & (NBUF - 1);
        const uint32_t phase = (s / NBUF) & 1;
        mbar_wait(mbar0 + buf * 8, phase);

        const char* wbase = smem + buf * ST_SIZE;
        const char* wb0 = wbase + rg * WSTRIDE + wid * 64;           // 16 k = 64B
        const char* wb1 = wbase + (rg + 16) * WSTRIDE + wid * 64;
        const char* xb  = wbase + W_REGION + (wid * 16) * XPITCH + h * 32;

        #pragma unroll
        for (int j = 0; j < 4; j++) {       // 4 int4 per row = 16 k
            int4 qa = ((const int4*)wb0)[j];
            int4 qb = ((const int4*)wb1)[j];
            #pragma unroll
            for (int u = 0; u < 4; u++) {
                int iva = (u == 0) ? qa.x : (u == 1) ? qa.y : (u == 2) ? qa.z : qa.w;
                int ivb = (u == 0) ? qb.x : (u == 1) ? qb.y : (u == 2) ? qb.z : qb.w;
                unsigned long long wa = pack2(__int2float_rn(iva));   // I2F: off fma pipe
                unsigned long long wb = pack2(__int2float_rn(ivb));
                const char* xr = xb + (j * 4 + u) * XPITCH;
                ulonglong2 p0 = *(const ulonglong2*)(xr);       // tokens h*8 .. +4
                ulonglong2 p1 = *(const ulonglong2*)(xr + 16);  // tokens h*8+4 .. +8
                ffma2(acc0[0], wa, p0.x);  ffma2(acc1[0], wb, p0.x);
                ffma2(acc0[1], wa, p0.y);  ffma2(acc1[1], wb, p0.y);
                ffma2(acc0[2], wa, p1.x);  ffma2(acc1[2], wb, p1.x);
                ffma2(acc0[3], wa, p1.y);  ffma2(acc1[3], wb, p1.y);
            }
        }

        __syncthreads();                 // CTA done with buf

        if (s + NBUF < SCNT && tid == 0) {
            const uint32_t mb = mbar0 + buf * 8;
            mbar_expect_tx(mb, TX_BYTES);
            tma_load_2d(sbase + buf * ST_SIZE, &wmap, (s + NBUF) * KT, o_base, mb);
            bulk_copy(sbase + buf * ST_SIZE + W_REGION,
                      g_xT + (s + NBUF) * KT * M_TOK, X_REGION, mb);
        }
    }

    // ---- reduce 8 warp-partials per (row, token) through smem ----
    float* part = (float*)smem;          // [(wid*32 + row)*17 + tok], 17.4 KB
    {
        float* pp0 = part + (wid * 32 + rg)      * 17 + h * 8;
        float* pp1 = part + (wid * 32 + rg + 16) * 17 + h * 8;
        #pragma unroll
        for (int i = 0; i < 4; i++) {
            float lo, hi;
            asm("mov.b64 {%0, %1}, %2;" : "=f"(lo), "=f"(hi) : "l"(acc0[i]));
            pp0[2 * i] = lo;  pp0[2 * i + 1] = hi;
            asm("mov.b64 {%0, %1}, %2;" : "=f"(lo), "=f"(hi) : "l"(acc1[i]));
            pp1[2 * i] = lo;  pp1[2 * i + 1] = hi;
        }
    }
    __syncthreads();

    #pragma unroll
    for (int r = 0; r < 2; r++) {
        int idx = tid + r * THREADS;     // 0..511
        int oo  = idx & 31;
        int tt  = idx >> 5;
        float v = 0.f;
        #pragma unroll
        for (int q = 0; q < 8; q++)
            v += part[(q * 32 + oo) * 17 + tt];
        float sx = 0.f;
        #pragma unroll
        for (int c = 0; c < 8; c++) sx += g_psum[tt * 8 + c];
        out[(size_t)tt * N_OUT + o_base + oo] = scale * (v - zpf * sx);
    }
}

// ---------------- host ----------------
typedef CUresult (*EncodeTiledFn)(
    CUtensorMap*, CUtensorMapDataType, cuuint32_t, void*,
    const cuuint64_t*, const cuuint64_t*, const cuuint32_t*, const cuuint32_t*,
    CUtensorMapInterleave, CUtensorMapSwizzle, CUtensorMapL2promotion,
    CUtensorMapFloatOOBfill);

static EncodeTiledFn get_encode_fn() {
    static EncodeTiledFn fn = nullptr;
    if (fn) return fn;
    void* p = nullptr;
#if CUDART_VERSION >= 12050
    cudaDriverEntryPointQueryResult st;
    if (cudaGetDriverEntryPointByVersion("cuTensorMapEncodeTiled", &p, 12000,
                                         cudaEnableDefault, &st) != cudaSuccess)
        p = nullptr;
#endif
    if (!p) {
        cudaDriverEntryPointQueryResult st2;
        cudaGetDriverEntryPoint("cuTensorMapEncodeTiled", &p,
                                cudaEnableDefault, &st2);
    }
    fn = (EncodeTiledFn)p;
    return fn;
}

extern "C" void kernel_launch(void* const* d_in, const int* in_sizes, int n_in,
                              void* d_out, int out_size) {
    const float* x  = nullptr;
    const int*   w  = nullptr;           // int8 weights marshaled as int32
    const float* sc = nullptr;
    const int*   zp = nullptr;
    for (int i = 0; i < n_in; i++) {
        long long n = in_sizes[i];
        if (n == W_ELEMS)       w  = (const int*)d_in[i];
        else if (n == X_ELEMS)  x  = (const float*)d_in[i];
        else if (!sc)           sc = (const float*)d_in[i];
        else                    zp = (const int*)d_in[i];
    }
    (void)out_size;

    static bool attr_set = false;
    if (!attr_set) {
        cudaFuncSetAttribute(gemm_kernel,
                             cudaFuncAttributeMaxDynamicSharedMemorySize, DYN_SMEM);
        attr_set = true;
    }

    CUtensorMap wmap;
    {
        EncodeTiledFn enc = get_encode_fn();
        cuuint64_t dims[2]    = {(cuuint64_t)K_DIM, (cuuint64_t)N_OUT};
        cuuint64_t strides[1] = {(cuuint64_t)K_DIM * 4};
        cuuint32_t box[2]     = {(cuuint32_t)WBOX0, (cuuint32_t)OTILE};
        cuuint32_t estr[2]    = {1, 1};
        enc(&wmap, CU_TENSOR_MAP_DATA_TYPE_UINT32, 2, (void*)w,
            dims, strides, box, estr,
            CU_TENSOR_MAP_INTERLEAVE_NONE, CU_TENSOR_MAP_SWIZZLE_NONE,
            CU_TENSOR_MAP_L2_PROMOTION_L2_128B,
            CU_TENSOR_MAP_FLOAT_OOB_FILL_NONE);
    }

    prep_kernel<<<128, 256>>>(x);
    gemm_kernel<<<NCTA, THREADS, DYN_SMEM>>>(wmap, sc, zp, (float*)d_out);
}